// round 4
// baseline (speedup 1.0000x reference)
#include <cuda_runtime.h>
#include <cuda_bf16.h>

#define N_NODES 50000
#define N_EDGES 1250000
#define D_NODE  64
#define D_EDGE  16
#define D_HID   64
#define D_IN1   80    // D_NODE + D_EDGE
#define D_IN2   128   // D_NODE + D_HID

// Scratch for segment-sum aggregation (no cudaMalloc allowed).
__device__ __align__(16) float g_agg[(size_t)N_NODES * D_HID];

// ---- packed fp32x2 helpers (sm_100+: dual-lane FFMA via PTX f32x2) --------
__device__ __forceinline__ unsigned long long pack2(float v) {
    unsigned long long r;
    unsigned int b = __float_as_uint(v);
    asm("mov.b64 %0, {%1, %1};" : "=l"(r) : "r"(b));
    return r;
}
__device__ __forceinline__ void fma2(unsigned long long& d,
                                     unsigned long long a,
                                     unsigned long long b) {
    asm("fma.rn.f32x2 %0, %1, %2, %0;" : "+l"(d) : "l"(a), "l"(b));
}
__device__ __forceinline__ void unpack2(unsigned long long v, float& lo, float& hi) {
    unsigned int l, h;
    asm("mov.b64 {%0, %1}, %2;" : "=r"(l), "=r"(h) : "l"(v));
    lo = __uint_as_float(l);
    hi = __uint_as_float(h);
}

__device__ __forceinline__ void red_add_v4(float* p, float a, float b, float c, float d) {
    asm volatile("red.global.add.v4.f32 [%0], {%1, %2, %3, %4};"
                 :: "l"(p), "f"(a), "f"(b), "f"(c), "f"(d) : "memory");
}

// ---------------------------------------------------------------------------
// Zero the aggregation buffer (12.8 MB) — trivial bandwidth cost.
// ---------------------------------------------------------------------------
__global__ void zero_agg_kernel() {
    int i = blockIdx.x * blockDim.x + threadIdx.x;
    const int n4 = (N_NODES * D_HID) / 4;
    if (i < n4) {
        float4 z = make_float4(0.f, 0.f, 0.f, 0.f);
        reinterpret_cast<float4*>(g_agg)[i] = z;
    }
}

// ---------------------------------------------------------------------------
// Phase 1: per-edge message MLP + scatter-add to destination nodes.
// One thread = one edge. Weights in shared (warp-broadcast LDS.128).
// Hidden accumulators kept as 32 packed f32x2 pairs; layer-2 in 16-wide
// output chunks (8 packed accumulators live at a time).
// ---------------------------------------------------------------------------
__global__ __launch_bounds__(256, 2)
void edge_kernel(const float* __restrict__ nf,   // [N, 64]
                 const float* __restrict__ ef,   // [E, 16]
                 const int*   __restrict__ ei,   // [2, E]
                 const float* __restrict__ w1,   // [80, 64]
                 const float* __restrict__ b1,   // [64]
                 const float* __restrict__ w2,   // [64, 64]
                 const float* __restrict__ b2)   // [64]
{
    __shared__ __align__(16) float s_w1[D_IN1 * D_HID];   // 20 KB
    __shared__ __align__(16) float s_w2[D_HID * D_HID];   // 16 KB

    const int tid = threadIdx.x;
    for (int i = tid; i < (D_IN1 * D_HID) / 4; i += 256)
        reinterpret_cast<float4*>(s_w1)[i] = reinterpret_cast<const float4*>(w1)[i];
    for (int i = tid; i < (D_HID * D_HID) / 4; i += 256)
        reinterpret_cast<float4*>(s_w2)[i] = reinterpret_cast<const float4*>(w2)[i];
    __syncthreads();

    const int e = blockIdx.x * 256 + tid;
    if (e >= N_EDGES) return;

    const int src = __ldg(&ei[e]);
    const int dst = __ldg(&ei[N_EDGES + e]);

    const float4* xs = reinterpret_cast<const float4*>(nf + (size_t)src * D_NODE);
    const float4* xe = reinterpret_cast<const float4*>(ef + (size_t)e * D_EDGE);

    // --- layer 1: h = relu(x @ w1 + b1), x = [src_feat(64) | edge_feat(16)]
    unsigned long long h2[32];   // 64 fp32 accumulators as 32 packed pairs
    {
        const ulonglong2* b1p = reinterpret_cast<const ulonglong2*>(b1);
        #pragma unroll
        for (int i = 0; i < 16; i++) {
            ulonglong2 b = __ldg(&b1p[i]);
            h2[2 * i] = b.x; h2[2 * i + 1] = b.y;
        }
    }

    // node-feature part of x: k = 0..63
    #pragma unroll 4
    for (int kc = 0; kc < 16; kc++) {
        float4 x = __ldg(&xs[kc]);
        float xv[4] = {x.x, x.y, x.z, x.w};
        #pragma unroll
        for (int kk = 0; kk < 4; kk++) {
            const unsigned long long vv = pack2(xv[kk]);
            const ulonglong2* wr =
                reinterpret_cast<const ulonglong2*>(&s_w1[(kc * 4 + kk) * D_HID]);
            #pragma unroll
            for (int j = 0; j < 16; j++) {
                ulonglong2 w = wr[j];
                fma2(h2[2 * j],     vv, w.x);
                fma2(h2[2 * j + 1], vv, w.y);
            }
        }
    }
    // edge-feature part of x: k = 64..79
    #pragma unroll
    for (int kc = 0; kc < 4; kc++) {
        float4 x = __ldg(&xe[kc]);
        float xv[4] = {x.x, x.y, x.z, x.w};
        #pragma unroll
        for (int kk = 0; kk < 4; kk++) {
            const unsigned long long vv = pack2(xv[kk]);
            const ulonglong2* wr =
                reinterpret_cast<const ulonglong2*>(&s_w1[(D_NODE + kc * 4 + kk) * D_HID]);
            #pragma unroll
            for (int j = 0; j < 16; j++) {
                ulonglong2 w = wr[j];
                fma2(h2[2 * j],     vv, w.x);
                fma2(h2[2 * j + 1], vv, w.y);
            }
        }
    }

    // relu + unpack
    float h[D_HID];
    #pragma unroll
    for (int i = 0; i < 32; i++) {
        float lo, hi;
        unpack2(h2[i], lo, hi);
        h[2 * i]     = fmaxf(lo, 0.f);
        h[2 * i + 1] = fmaxf(hi, 0.f);
    }

    // --- layer 2: msg = h @ w2 + b2, reduced directly into g_agg[dst]
    float* aggp = &g_agg[(size_t)dst * D_HID];
    #pragma unroll
    for (int jc = 0; jc < 4; jc++) {           // 4 chunks of 16 outputs
        unsigned long long acc2[8];
        {
            const ulonglong2* b2p = reinterpret_cast<const ulonglong2*>(&b2[jc * 16]);
            #pragma unroll
            for (int i = 0; i < 4; i++) {
                ulonglong2 b = __ldg(&b2p[i]);
                acc2[2 * i] = b.x; acc2[2 * i + 1] = b.y;
            }
        }
        #pragma unroll 8
        for (int k = 0; k < D_HID; k++) {
            const unsigned long long vv = pack2(h[k]);
            const ulonglong2* wr =
                reinterpret_cast<const ulonglong2*>(&s_w2[k * D_HID + jc * 16]);
            #pragma unroll
            for (int i = 0; i < 4; i++) {
                ulonglong2 w = wr[i];
                fma2(acc2[2 * i],     vv, w.x);
                fma2(acc2[2 * i + 1], vv, w.y);
            }
        }
        float acc[16];
        #pragma unroll
        for (int i = 0; i < 8; i++) unpack2(acc2[i], acc[2 * i], acc[2 * i + 1]);
        red_add_v4(aggp + jc * 16 + 0,  acc[0],  acc[1],  acc[2],  acc[3]);
        red_add_v4(aggp + jc * 16 + 4,  acc[4],  acc[5],  acc[6],  acc[7]);
        red_add_v4(aggp + jc * 16 + 8,  acc[8],  acc[9],  acc[10], acc[11]);
        red_add_v4(aggp + jc * 16 + 12, acc[12], acc[13], acc[14], acc[15]);
    }
}

// ---------------------------------------------------------------------------
// Phase 2: per-node update MLP. One thread = one node. Same f32x2 scheme.
// ---------------------------------------------------------------------------
__global__ __launch_bounds__(256, 2)
void node_kernel(const float* __restrict__ nf,   // [N, 64]
                 const float* __restrict__ w1,   // [128, 64]
                 const float* __restrict__ b1,   // [64]
                 const float* __restrict__ w2,   // [64, 64]
                 const float* __restrict__ b2,   // [64]
                 float*       __restrict__ out)  // [N, 64]
{
    __shared__ __align__(16) float s_w1[D_IN2 * D_HID];   // 32 KB
    __shared__ __align__(16) float s_w2[D_HID * D_HID];   // 16 KB (48 KB total)

    const int tid = threadIdx.x;
    for (int i = tid; i < (D_IN2 * D_HID) / 4; i += 256)
        reinterpret_cast<float4*>(s_w1)[i] = reinterpret_cast<const float4*>(w1)[i];
    for (int i = tid; i < (D_HID * D_HID) / 4; i += 256)
        reinterpret_cast<float4*>(s_w2)[i] = reinterpret_cast<const float4*>(w2)[i];
    __syncthreads();

    const int n = blockIdx.x * 256 + tid;
    if (n >= N_NODES) return;

    const float4* xn = reinterpret_cast<const float4*>(nf + (size_t)n * D_NODE);
    const float4* xa = reinterpret_cast<const float4*>(&g_agg[(size_t)n * D_HID]);

    unsigned long long h2[32];
    {
        const ulonglong2* b1p = reinterpret_cast<const ulonglong2*>(b1);
        #pragma unroll
        for (int i = 0; i < 16; i++) {
            ulonglong2 b = __ldg(&b1p[i]);
            h2[2 * i] = b.x; h2[2 * i + 1] = b.y;
        }
    }

    // k = 0..63 : node features
    #pragma unroll 4
    for (int kc = 0; kc < 16; kc++) {
        float4 x = __ldg(&xn[kc]);
        float xv[4] = {x.x, x.y, x.z, x.w};
        #pragma unroll
        for (int kk = 0; kk < 4; kk++) {
            const unsigned long long vv = pack2(xv[kk]);
            const ulonglong2* wr =
                reinterpret_cast<const ulonglong2*>(&s_w1[(kc * 4 + kk) * D_HID]);
            #pragma unroll
            for (int j = 0; j < 16; j++) {
                ulonglong2 w = wr[j];
                fma2(h2[2 * j],     vv, w.x);
                fma2(h2[2 * j + 1], vv, w.y);
            }
        }
    }
    // k = 64..127 : aggregated messages
    #pragma unroll 4
    for (int kc = 0; kc < 16; kc++) {
        float4 x = xa[kc];
        float xv[4] = {x.x, x.y, x.z, x.w};
        #pragma unroll
        for (int kk = 0; kk < 4; kk++) {
            const unsigned long long vv = pack2(xv[kk]);
            const ulonglong2* wr =
                reinterpret_cast<const ulonglong2*>(&s_w1[(D_NODE + kc * 4 + kk) * D_HID]);
            #pragma unroll
            for (int j = 0; j < 16; j++) {
                ulonglong2 w = wr[j];
                fma2(h2[2 * j],     vv, w.x);
                fma2(h2[2 * j + 1], vv, w.y);
            }
        }
    }

    float h[D_HID];
    #pragma unroll
    for (int i = 0; i < 32; i++) {
        float lo, hi;
        unpack2(h2[i], lo, hi);
        h[2 * i]     = fmaxf(lo, 0.f);
        h[2 * i + 1] = fmaxf(hi, 0.f);
    }

    float* outp = out + (size_t)n * D_HID;
    #pragma unroll
    for (int jc = 0; jc < 4; jc++) {
        unsigned long long acc2[8];
        {
            const ulonglong2* b2p = reinterpret_cast<const ulonglong2*>(&b2[jc * 16]);
            #pragma unroll
            for (int i = 0; i < 4; i++) {
                ulonglong2 b = __ldg(&b2p[i]);
                acc2[2 * i] = b.x; acc2[2 * i + 1] = b.y;
            }
        }
        #pragma unroll 8
        for (int k = 0; k < D_HID; k++) {
            const unsigned long long vv = pack2(h[k]);
            const ulonglong2* wr =
                reinterpret_cast<const ulonglong2*>(&s_w2[k * D_HID + jc * 16]);
            #pragma unroll
            for (int i = 0; i < 4; i++) {
                ulonglong2 w = wr[i];
                fma2(acc2[2 * i],     vv, w.x);
                fma2(acc2[2 * i + 1], vv, w.y);
            }
        }
        float acc[16];
        #pragma unroll
        for (int i = 0; i < 8; i++) unpack2(acc2[i], acc[2 * i], acc[2 * i + 1]);
        #pragma unroll
        for (int j = 0; j < 16; j += 4) {
            float4 v = make_float4(acc[j], acc[j + 1], acc[j + 2], acc[j + 3]);
            *reinterpret_cast<float4*>(&outp[jc * 16 + j]) = v;
        }
    }
}

// ---------------------------------------------------------------------------
// Launch. Input order (metadata): node_features, edge_features, edge_index,
// w_m1, b_m1, w_m2, b_m2, w_u1, b_u1, w_u2, b_u2. Output: float32 [N, 64].
// ---------------------------------------------------------------------------
extern "C" void kernel_launch(void* const* d_in, const int* in_sizes, int n_in,
                              void* d_out, int out_size) {
    const float* nf   = (const float*)d_in[0];
    const float* ef   = (const float*)d_in[1];
    const int*   ei   = (const int*)  d_in[2];
    const float* w_m1 = (const float*)d_in[3];
    const float* b_m1 = (const float*)d_in[4];
    const float* w_m2 = (const float*)d_in[5];
    const float* b_m2 = (const float*)d_in[6];
    const float* w_u1 = (const float*)d_in[7];
    const float* b_u1 = (const float*)d_in[8];
    const float* w_u2 = (const float*)d_in[9];
    const float* b_u2 = (const float*)d_in[10];
    float* out = (float*)d_out;

    (void)in_sizes; (void)n_in; (void)out_size;

    {
        const int n4 = (N_NODES * D_HID) / 4;
        zero_agg_kernel<<<(n4 + 255) / 256, 256>>>();
    }
    {
        const int grid = (N_EDGES + 255) / 256;
        edge_kernel<<<grid, 256>>>(nf, ef, ei, w_m1, b_m1, w_m2, b_m2);
    }
    {
        const int grid = (N_NODES + 255) / 256;
        node_kernel<<<grid, 256>>>(nf, w_u1, b_u1, w_u2, b_u2, out);
    }
}

// round 5
// speedup vs baseline: 1.0286x; 1.0286x over previous
#include <cuda_runtime.h>
#include <cuda_bf16.h>

#define N_NODES 50000
#define N_EDGES 1250000
#define D_NODE  64
#define D_EDGE  16
#define D_HID   64
#define D_IN1   80    // D_NODE + D_EDGE
#define D_IN2   128   // D_NODE + D_HID
#define BLK     192   // 65536 regs / (192*2) = 170 regs/thread -> no spills

// Scratch for segment-sum aggregation. Zero-initialized at module load;
// node_kernel re-zeroes each row after consuming it, so the invariant
// "g_agg == 0 at kernel_launch entry" holds across graph replays.
__device__ __align__(16) float g_agg[(size_t)N_NODES * D_HID];

// ---- packed fp32x2 helpers (sm_100+: dual-lane FFMA via PTX f32x2) --------
__device__ __forceinline__ unsigned long long pack2(float v) {
    unsigned long long r;
    unsigned int b = __float_as_uint(v);
    asm("mov.b64 %0, {%1, %1};" : "=l"(r) : "r"(b));
    return r;
}
__device__ __forceinline__ void fma2(unsigned long long& d,
                                     unsigned long long a,
                                     unsigned long long b) {
    asm("fma.rn.f32x2 %0, %1, %2, %0;" : "+l"(d) : "l"(a), "l"(b));
}
__device__ __forceinline__ void unpack2(unsigned long long v, float& lo, float& hi) {
    unsigned int l, h;
    asm("mov.b64 {%0, %1}, %2;" : "=r"(l), "=r"(h) : "l"(v));
    lo = __uint_as_float(l);
    hi = __uint_as_float(h);
}

__device__ __forceinline__ void red_add_v4(float* p, float a, float b, float c, float d) {
    asm volatile("red.global.add.v4.f32 [%0], {%1, %2, %3, %4};"
                 :: "l"(p), "f"(a), "f"(b), "f"(c), "f"(d) : "memory");
}

// ---------------------------------------------------------------------------
// Phase 1: per-edge message MLP + scatter-add to destination nodes.
// One thread = one edge. Weights in shared (warp-broadcast LDS.128).
// ---------------------------------------------------------------------------
__global__ __launch_bounds__(BLK, 2)
void edge_kernel(const float* __restrict__ nf,   // [N, 64]
                 const float* __restrict__ ef,   // [E, 16]
                 const int*   __restrict__ ei,   // [2, E]
                 const float* __restrict__ w1,   // [80, 64]
                 const float* __restrict__ b1,   // [64]
                 const float* __restrict__ w2,   // [64, 64]
                 const float* __restrict__ b2)   // [64]
{
    __shared__ __align__(16) float s_w1[D_IN1 * D_HID];   // 20 KB
    __shared__ __align__(16) float s_w2[D_HID * D_HID];   // 16 KB

    const int tid = threadIdx.x;
    for (int i = tid; i < (D_IN1 * D_HID) / 4; i += BLK)
        reinterpret_cast<float4*>(s_w1)[i] = reinterpret_cast<const float4*>(w1)[i];
    for (int i = tid; i < (D_HID * D_HID) / 4; i += BLK)
        reinterpret_cast<float4*>(s_w2)[i] = reinterpret_cast<const float4*>(w2)[i];
    __syncthreads();

    const int e = blockIdx.x * BLK + tid;
    if (e >= N_EDGES) return;

    const int src = __ldg(&ei[e]);
    const int dst = __ldg(&ei[N_EDGES + e]);

    const float4* xs = reinterpret_cast<const float4*>(nf + (size_t)src * D_NODE);
    const float4* xe = reinterpret_cast<const float4*>(ef + (size_t)e * D_EDGE);

    // --- layer 1: h = relu(x @ w1 + b1), x = [src_feat(64) | edge_feat(16)]
    unsigned long long h2[32];   // 64 fp32 accumulators as 32 packed pairs
    {
        const ulonglong2* b1p = reinterpret_cast<const ulonglong2*>(b1);
        #pragma unroll
        for (int i = 0; i < 16; i++) {
            ulonglong2 b = __ldg(&b1p[i]);
            h2[2 * i] = b.x; h2[2 * i + 1] = b.y;
        }
    }

    // node-feature part of x: k = 0..63
    #pragma unroll 4
    for (int kc = 0; kc < 16; kc++) {
        float4 x = __ldg(&xs[kc]);
        float xv[4] = {x.x, x.y, x.z, x.w};
        #pragma unroll
        for (int kk = 0; kk < 4; kk++) {
            const unsigned long long vv = pack2(xv[kk]);
            const ulonglong2* wr =
                reinterpret_cast<const ulonglong2*>(&s_w1[(kc * 4 + kk) * D_HID]);
            // two 8-wide halves to limit in-flight weight registers
            #pragma unroll
            for (int j = 0; j < 8; j++) {
                ulonglong2 w = wr[j];
                fma2(h2[2 * j],     vv, w.x);
                fma2(h2[2 * j + 1], vv, w.y);
            }
            #pragma unroll
            for (int j = 8; j < 16; j++) {
                ulonglong2 w = wr[j];
                fma2(h2[2 * j],     vv, w.x);
                fma2(h2[2 * j + 1], vv, w.y);
            }
        }
    }
    // edge-feature part of x: k = 64..79
    #pragma unroll
    for (int kc = 0; kc < 4; kc++) {
        float4 x = __ldg(&xe[kc]);
        float xv[4] = {x.x, x.y, x.z, x.w};
        #pragma unroll
        for (int kk = 0; kk < 4; kk++) {
            const unsigned long long vv = pack2(xv[kk]);
            const ulonglong2* wr =
                reinterpret_cast<const ulonglong2*>(&s_w1[(D_NODE + kc * 4 + kk) * D_HID]);
            #pragma unroll
            for (int j = 0; j < 8; j++) {
                ulonglong2 w = wr[j];
                fma2(h2[2 * j],     vv, w.x);
                fma2(h2[2 * j + 1], vv, w.y);
            }
            #pragma unroll
            for (int j = 8; j < 16; j++) {
                ulonglong2 w = wr[j];
                fma2(h2[2 * j],     vv, w.x);
                fma2(h2[2 * j + 1], vv, w.y);
            }
        }
    }

    // relu + unpack (h2 dies here; h takes its registers)
    float h[D_HID];
    #pragma unroll
    for (int i = 0; i < 32; i++) {
        float lo, hi;
        unpack2(h2[i], lo, hi);
        h[2 * i]     = fmaxf(lo, 0.f);
        h[2 * i + 1] = fmaxf(hi, 0.f);
    }

    // --- layer 2: msg = h @ w2 + b2, reduced directly into g_agg[dst]
    float* aggp = &g_agg[(size_t)dst * D_HID];
    #pragma unroll
    for (int jc = 0; jc < 4; jc++) {           // 4 chunks of 16 outputs
        unsigned long long acc2[8];
        {
            const ulonglong2* b2p = reinterpret_cast<const ulonglong2*>(&b2[jc * 16]);
            #pragma unroll
            for (int i = 0; i < 4; i++) {
                ulonglong2 b = __ldg(&b2p[i]);
                acc2[2 * i] = b.x; acc2[2 * i + 1] = b.y;
            }
        }
        #pragma unroll 8
        for (int k = 0; k < D_HID; k++) {
            const unsigned long long vv = pack2(h[k]);
            const ulonglong2* wr =
                reinterpret_cast<const ulonglong2*>(&s_w2[k * D_HID + jc * 16]);
            #pragma unroll
            for (int i = 0; i < 4; i++) {
                ulonglong2 w = wr[i];
                fma2(acc2[2 * i],     vv, w.x);
                fma2(acc2[2 * i + 1], vv, w.y);
            }
        }
        float acc[16];
        #pragma unroll
        for (int i = 0; i < 8; i++) unpack2(acc2[i], acc[2 * i], acc[2 * i + 1]);
        red_add_v4(aggp + jc * 16 + 0,  acc[0],  acc[1],  acc[2],  acc[3]);
        red_add_v4(aggp + jc * 16 + 4,  acc[4],  acc[5],  acc[6],  acc[7]);
        red_add_v4(aggp + jc * 16 + 8,  acc[8],  acc[9],  acc[10], acc[11]);
        red_add_v4(aggp + jc * 16 + 12, acc[12], acc[13], acc[14], acc[15]);
    }
}

// ---------------------------------------------------------------------------
// Phase 2: per-node update MLP. One thread = one node.
// Also re-zeroes this node's g_agg row after reading it (keeps the
// "agg buffer is zero at entry" invariant for the next graph replay).
// ---------------------------------------------------------------------------
__global__ __launch_bounds__(BLK, 2)
void node_kernel(const float* __restrict__ nf,   // [N, 64]
                 const float* __restrict__ w1,   // [128, 64]
                 const float* __restrict__ b1,   // [64]
                 const float* __restrict__ w2,   // [64, 64]
                 const float* __restrict__ b2,   // [64]
                 float*       __restrict__ out)  // [N, 64]
{
    __shared__ __align__(16) float s_w1[D_IN2 * D_HID];   // 32 KB
    __shared__ __align__(16) float s_w2[D_HID * D_HID];   // 16 KB (48 KB total)

    const int tid = threadIdx.x;
    for (int i = tid; i < (D_IN2 * D_HID) / 4; i += BLK)
        reinterpret_cast<float4*>(s_w1)[i] = reinterpret_cast<const float4*>(w1)[i];
    for (int i = tid; i < (D_HID * D_HID) / 4; i += BLK)
        reinterpret_cast<float4*>(s_w2)[i] = reinterpret_cast<const float4*>(w2)[i];
    __syncthreads();

    const int n = blockIdx.x * BLK + tid;
    if (n >= N_NODES) return;

    const float4* xn = reinterpret_cast<const float4*>(nf + (size_t)n * D_NODE);
    float4*       xa = reinterpret_cast<float4*>(&g_agg[(size_t)n * D_HID]);

    unsigned long long h2[32];
    {
        const ulonglong2* b1p = reinterpret_cast<const ulonglong2*>(b1);
        #pragma unroll
        for (int i = 0; i < 16; i++) {
            ulonglong2 b = __ldg(&b1p[i]);
            h2[2 * i] = b.x; h2[2 * i + 1] = b.y;
        }
    }

    // k = 0..63 : node features
    #pragma unroll 4
    for (int kc = 0; kc < 16; kc++) {
        float4 x = __ldg(&xn[kc]);
        float xv[4] = {x.x, x.y, x.z, x.w};
        #pragma unroll
        for (int kk = 0; kk < 4; kk++) {
            const unsigned long long vv = pack2(xv[kk]);
            const ulonglong2* wr =
                reinterpret_cast<const ulonglong2*>(&s_w1[(kc * 4 + kk) * D_HID]);
            #pragma unroll
            for (int j = 0; j < 8; j++) {
                ulonglong2 w = wr[j];
                fma2(h2[2 * j],     vv, w.x);
                fma2(h2[2 * j + 1], vv, w.y);
            }
            #pragma unroll
            for (int j = 8; j < 16; j++) {
                ulonglong2 w = wr[j];
                fma2(h2[2 * j],     vv, w.x);
                fma2(h2[2 * j + 1], vv, w.y);
            }
        }
    }
    // k = 64..127 : aggregated messages (read, then zero the row)
    #pragma unroll 4
    for (int kc = 0; kc < 16; kc++) {
        float4 x = xa[kc];
        xa[kc] = make_float4(0.f, 0.f, 0.f, 0.f);   // reset for next replay
        float xv[4] = {x.x, x.y, x.z, x.w};
        #pragma unroll
        for (int kk = 0; kk < 4; kk++) {
            const unsigned long long vv = pack2(xv[kk]);
            const ulonglong2* wr =
                reinterpret_cast<const ulonglong2*>(&s_w1[(D_NODE + kc * 4 + kk) * D_HID]);
            #pragma unroll
            for (int j = 0; j < 8; j++) {
                ulonglong2 w = wr[j];
                fma2(h2[2 * j],     vv, w.x);
                fma2(h2[2 * j + 1], vv, w.y);
            }
            #pragma unroll
            for (int j = 8; j < 16; j++) {
                ulonglong2 w = wr[j];
                fma2(h2[2 * j],     vv, w.x);
                fma2(h2[2 * j + 1], vv, w.y);
            }
        }
    }

    float h[D_HID];
    #pragma unroll
    for (int i = 0; i < 32; i++) {
        float lo, hi;
        unpack2(h2[i], lo, hi);
        h[2 * i]     = fmaxf(lo, 0.f);
        h[2 * i + 1] = fmaxf(hi, 0.f);
    }

    float* outp = out + (size_t)n * D_HID;
    #pragma unroll
    for (int jc = 0; jc < 4; jc++) {
        unsigned long long acc2[8];
        {
            const ulonglong2* b2p = reinterpret_cast<const ulonglong2*>(&b2[jc * 16]);
            #pragma unroll
            for (int i = 0; i < 4; i++) {
                ulonglong2 b = __ldg(&b2p[i]);
                acc2[2 * i] = b.x; acc2[2 * i + 1] = b.y;
            }
        }
        #pragma unroll 8
        for (int k = 0; k < D_HID; k++) {
            const unsigned long long vv = pack2(h[k]);
            const ulonglong2* wr =
                reinterpret_cast<const ulonglong2*>(&s_w2[k * D_HID + jc * 16]);
            #pragma unroll
            for (int i = 0; i < 4; i++) {
                ulonglong2 w = wr[i];
                fma2(acc2[2 * i],     vv, w.x);
                fma2(acc2[2 * i + 1], vv, w.y);
            }
        }
        float acc[16];
        #pragma unroll
        for (int i = 0; i < 8; i++) unpack2(acc2[i], acc[2 * i], acc[2 * i + 1]);
        #pragma unroll
        for (int j = 0; j < 16; j += 4) {
            float4 v = make_float4(acc[j], acc[j + 1], acc[j + 2], acc[j + 3]);
            *reinterpret_cast<float4*>(&outp[jc * 16 + j]) = v;
        }
    }
}

// ---------------------------------------------------------------------------
// Launch. Input order (metadata): node_features, edge_features, edge_index,
// w_m1, b_m1, w_m2, b_m2, w_u1, b_u1, w_u2, b_u2. Output: float32 [N, 64].
// ---------------------------------------------------------------------------
extern "C" void kernel_launch(void* const* d_in, const int* in_sizes, int n_in,
                              void* d_out, int out_size) {
    const float* nf   = (const float*)d_in[0];
    const float* ef   = (const float*)d_in[1];
    const int*   ei   = (const int*)  d_in[2];
    const float* w_m1 = (const float*)d_in[3];
    const float* b_m1 = (const float*)d_in[4];
    const float* w_m2 = (const float*)d_in[5];
    const float* b_m2 = (const float*)d_in[6];
    const float* w_u1 = (const float*)d_in[7];
    const float* b_u1 = (const float*)d_in[8];
    const float* w_u2 = (const float*)d_in[9];
    const float* b_u2 = (const float*)d_in[10];
    float* out = (float*)d_out;

    (void)in_sizes; (void)n_in; (void)out_size;

    {
        const int grid = (N_EDGES + BLK - 1) / BLK;
        edge_kernel<<<grid, BLK>>>(nf, ef, ei, w_m1, b_m1, w_m2, b_m2);
    }
    {
        const int grid = (N_NODES + BLK - 1) / BLK;
        node_kernel<<<grid, BLK>>>(nf, w_u1, b_u1, w_u2, b_u2, out);
    }
}

// round 7
// speedup vs baseline: 1.4271x; 1.3874x over previous
#include <cuda_runtime.h>
#include <cuda_bf16.h>

#define N_NODES 50000
#define N_EDGES 1250000
#define D_NODE  64
#define D_EDGE  16
#define D_HID   64
#define K1      80    // D_NODE + D_EDGE
#define D_IN2   128   // D_NODE + D_HID

// ---- edge-kernel tiling ----
#define TM      128   // edges per block
#define LDX     132   // padded row stride (floats) for transposed x / h tiles
#define ETHREADS 256  // 16 x 16

// node kernel config
#define NBLK    192

// Scratch for segment-sum aggregation. Zero-initialized at module load;
// node_kernel re-zeroes each row after consuming it, so the invariant
// "g_agg == 0 at kernel_launch entry" holds across graph replays.
__device__ __align__(16) float g_agg[(size_t)N_NODES * D_HID];

// ---- packed fp32x2 helpers (sm_100+: dual-lane FFMA via PTX f32x2) --------
__device__ __forceinline__ unsigned long long pack2(float v) {
    unsigned long long r;
    unsigned int b = __float_as_uint(v);
    asm("mov.b64 %0, {%1, %1};" : "=l"(r) : "r"(b));
    return r;
}
__device__ __forceinline__ void fma2(unsigned long long& d,
                                     unsigned long long a,
                                     unsigned long long b) {
    asm("fma.rn.f32x2 %0, %1, %2, %0;" : "+l"(d) : "l"(a), "l"(b));
}
__device__ __forceinline__ void unpack2(unsigned long long v, float& lo, float& hi) {
    unsigned int l, h;
    asm("mov.b64 {%0, %1}, %2;" : "=r"(l), "=r"(h) : "l"(v));
    lo = __uint_as_float(l);
    hi = __uint_as_float(h);
}
__device__ __forceinline__ void red_add_v4(float* p, float a, float b, float c, float d) {
    asm volatile("red.global.add.v4.f32 [%0], {%1, %2, %3, %4};"
                 :: "l"(p), "f"(a), "f"(b), "f"(c), "f"(d) : "memory");
}

// Dynamic smem layout (floats):
//   sx  : [K1][LDX]            10560   (reused as hT[64][LDX] for layer 2)
//   sw1 : [K1][D_HID]           5120
//   sw2 : [D_HID][D_HID]        4096
//   ssrc: [TM] ints              128
//   sdst: [TM] ints              128
#define SX_OFF   0
#define SW1_OFF  (K1 * LDX)
#define SW2_OFF  (SW1_OFF + K1 * D_HID)
#define SRC_OFF  (SW2_OFF + D_HID * D_HID)
#define DST_OFF  (SRC_OFF + TM)
#define EDGE_SMEM_FLOATS (DST_OFF + TM)
#define EDGE_SMEM_BYTES  (EDGE_SMEM_FLOATS * 4)   // 80128

// ---------------------------------------------------------------------------
// Phase 1: tiled edge message MLP + scatter-add.
// Block = 128 edges; thread (tx,ty) computes an 8-edge x 4-hid tile.
// Inputs staged transposed (xT[k][m]) so f32x2 packs over m with zero movs.
// ---------------------------------------------------------------------------
__global__ __launch_bounds__(ETHREADS, 2)
void edge_kernel(const float* __restrict__ nf,   // [N, 64]
                 const float* __restrict__ ef,   // [E, 16]
                 const int*   __restrict__ ei,   // [2, E]
                 const float* __restrict__ w1,   // [80, 64]
                 const float* __restrict__ b1,   // [64]
                 const float* __restrict__ w2,   // [64, 64]
                 const float* __restrict__ b2)   // [64]
{
    extern __shared__ __align__(16) float smem[];
    float* sx  = smem + SX_OFF;
    float* sw1 = smem + SW1_OFF;
    float* sw2 = smem + SW2_OFF;
    int*   ssrc = (int*)(smem + SRC_OFF);
    int*   sdst = (int*)(smem + DST_OFF);

    const int tid = threadIdx.x;
    const int tx = tid & 15;        // output-column group: cols 4tx..4tx+3
    const int ty = tid >> 4;        // edge group: edges 8ty..8ty+7
    const int edge_base = blockIdx.x * TM;

    // --- stage edge indices (clamped; invalid edges masked at scatter) ---
    {
        int m = tid & 127;
        int e = edge_base + m;
        if (e >= N_EDGES) e = N_EDGES - 1;
        if (tid < 128) ssrc[m] = __ldg(&ei[e]);
        else           sdst[m] = __ldg(&ei[N_EDGES + e]);
    }
    // --- stage weights (no dependence on indices) ---
    for (int i = tid; i < (K1 * D_HID) / 4; i += ETHREADS)
        reinterpret_cast<float4*>(sw1)[i] = __ldg(&reinterpret_cast<const float4*>(w1)[i]);
    for (int i = tid; i < (D_HID * D_HID) / 4; i += ETHREADS)
        reinterpret_cast<float4*>(sw2)[i] = __ldg(&reinterpret_cast<const float4*>(w2)[i]);
    __syncthreads();

    // --- gather + transpose inputs: xT[k][m], k = [node 64 | edge 16] ---
    {
        int m    = tid & 127;
        int half = tid >> 7;        // 2 threads per edge
        const float4* np = reinterpret_cast<const float4*>(nf + (size_t)ssrc[m] * D_NODE);
        #pragma unroll
        for (int q = 0; q < 8; q++) {
            int qq = half * 8 + q;
            float4 v = __ldg(&np[qq]);
            sx[(qq * 4 + 0) * LDX + m] = v.x;
            sx[(qq * 4 + 1) * LDX + m] = v.y;
            sx[(qq * 4 + 2) * LDX + m] = v.z;
            sx[(qq * 4 + 3) * LDX + m] = v.w;
        }
        int e = edge_base + m;
        if (e >= N_EDGES) e = N_EDGES - 1;
        const float4* ep = reinterpret_cast<const float4*>(ef + (size_t)e * D_EDGE);
        #pragma unroll
        for (int q = 0; q < 2; q++) {
            int qq = half * 2 + q;
            float4 v = __ldg(&ep[qq]);
            sx[(D_NODE + qq * 4 + 0) * LDX + m] = v.x;
            sx[(D_NODE + qq * 4 + 1) * LDX + m] = v.y;
            sx[(D_NODE + qq * 4 + 2) * LDX + m] = v.z;
            sx[(D_NODE + qq * 4 + 3) * LDX + m] = v.w;
        }
    }
    __syncthreads();

    const float* xbase = sx + ty * 8;

    // --- layer 1: acc[n][mq] over K1=80, f32x2 packed over m ---
    unsigned long long acc[4][4];
    {
        float4 bv = __ldg(reinterpret_cast<const float4*>(b1 + tx * 4));
        unsigned long long b0 = pack2(bv.x), b1p = pack2(bv.y),
                           b2p = pack2(bv.z), b3p = pack2(bv.w);
        #pragma unroll
        for (int mq = 0; mq < 4; mq++) {
            acc[0][mq] = b0; acc[1][mq] = b1p; acc[2][mq] = b2p; acc[3][mq] = b3p;
        }
    }
    #pragma unroll 2
    for (int k = 0; k < K1; k++) {
        ulonglong2 xa = *reinterpret_cast<const ulonglong2*>(xbase + k * LDX);
        ulonglong2 xb = *reinterpret_cast<const ulonglong2*>(xbase + k * LDX + 4);
        float4 wv = *reinterpret_cast<const float4*>(sw1 + k * D_HID + tx * 4);
        unsigned long long w0 = pack2(wv.x), w1p = pack2(wv.y),
                           w2p = pack2(wv.z), w3p = pack2(wv.w);
        fma2(acc[0][0], xa.x, w0);  fma2(acc[0][1], xa.y, w0);
        fma2(acc[0][2], xb.x, w0);  fma2(acc[0][3], xb.y, w0);
        fma2(acc[1][0], xa.x, w1p); fma2(acc[1][1], xa.y, w1p);
        fma2(acc[1][2], xb.x, w1p); fma2(acc[1][3], xb.y, w1p);
        fma2(acc[2][0], xa.x, w2p); fma2(acc[2][1], xa.y, w2p);
        fma2(acc[2][2], xb.x, w2p); fma2(acc[2][3], xb.y, w2p);
        fma2(acc[3][0], xa.x, w3p); fma2(acc[3][1], xa.y, w3p);
        fma2(acc[3][2], xb.x, w3p); fma2(acc[3][3], xb.y, w3p);
    }
    __syncthreads();   // everyone done reading sx

    // --- relu + restage h transposed: hT[k2][m], k2 = 4tx+n ---
    #pragma unroll
    for (int n = 0; n < 4; n++) {
        #pragma unroll
        for (int mq2 = 0; mq2 < 2; mq2++) {
            float f0, f1, f2, f3;
            unpack2(acc[n][2 * mq2],     f0, f1);
            unpack2(acc[n][2 * mq2 + 1], f2, f3);
            float4 v = make_float4(fmaxf(f0, 0.f), fmaxf(f1, 0.f),
                                   fmaxf(f2, 0.f), fmaxf(f3, 0.f));
            *reinterpret_cast<float4*>(sx + (tx * 4 + n) * LDX + ty * 8 + mq2 * 4) = v;
        }
    }
    __syncthreads();

    // --- layer 2: same tile shape over K=64 ---
    unsigned long long acc2[4][4];
    {
        float4 bv = __ldg(reinterpret_cast<const float4*>(b2 + tx * 4));
        unsigned long long b0 = pack2(bv.x), b1p = pack2(bv.y),
                           b2p = pack2(bv.z), b3p = pack2(bv.w);
        #pragma unroll
        for (int mq = 0; mq < 4; mq++) {
            acc2[0][mq] = b0; acc2[1][mq] = b1p; acc2[2][mq] = b2p; acc2[3][mq] = b3p;
        }
    }
    #pragma unroll 2
    for (int k = 0; k < D_HID; k++) {
        ulonglong2 xa = *reinterpret_cast<const ulonglong2*>(xbase + k * LDX);
        ulonglong2 xb = *reinterpret_cast<const ulonglong2*>(xbase + k * LDX + 4);
        float4 wv = *reinterpret_cast<const float4*>(sw2 + k * D_HID + tx * 4);
        unsigned long long w0 = pack2(wv.x), w1p = pack2(wv.y),
                           w2p = pack2(wv.z), w3p = pack2(wv.w);
        fma2(acc2[0][0], xa.x, w0);  fma2(acc2[0][1], xa.y, w0);
        fma2(acc2[0][2], xb.x, w0);  fma2(acc2[0][3], xb.y, w0);
        fma2(acc2[1][0], xa.x, w1p); fma2(acc2[1][1], xa.y, w1p);
        fma2(acc2[1][2], xb.x, w1p); fma2(acc2[1][3], xb.y, w1p);
        fma2(acc2[2][0], xa.x, w2p); fma2(acc2[2][1], xa.y, w2p);
        fma2(acc2[2][2], xb.x, w2p); fma2(acc2[2][3], xb.y, w2p);
        fma2(acc2[3][0], xa.x, w3p); fma2(acc2[3][1], xa.y, w3p);
        fma2(acc2[3][2], xb.x, w3p); fma2(acc2[3][3], xb.y, w3p);
    }

    // --- scatter: lanes tx=0..15 cover one edge's contiguous 64-float row ---
    #pragma unroll
    for (int mq = 0; mq < 4; mq++) {        // m pair (2mq, 2mq+1) within tile
        float a0, c0, a1, c1, a2, c2, a3, c3;
        unpack2(acc2[0][mq], a0, c0);
        unpack2(acc2[1][mq], a1, c1);
        unpack2(acc2[2][mq], a2, c2);
        unpack2(acc2[3][mq], a3, c3);
        int m0 = ty * 8 + 2 * mq;
        int e0 = edge_base + m0;
        if (e0 < N_EDGES)
            red_add_v4(&g_agg[(size_t)sdst[m0] * D_HID + tx * 4], a0, a1, a2, a3);
        if (e0 + 1 < N_EDGES)
            red_add_v4(&g_agg[(size_t)sdst[m0 + 1] * D_HID + tx * 4], c0, c1, c2, c3);
    }
}

// ---------------------------------------------------------------------------
// Phase 2: per-node update MLP (66us in R5; 7% of total).
// Re-zeroes this node's g_agg row after reading it.
// ---------------------------------------------------------------------------
__global__ __launch_bounds__(NBLK, 2)
void node_kernel(const float* __restrict__ nf,   // [N, 64]
                 const float* __restrict__ w1,   // [128, 64]
                 const float* __restrict__ b1,   // [64]
                 const float* __restrict__ w2,   // [64, 64]
                 const float* __restrict__ b2,   // [64]
                 float*       __restrict__ out)  // [N, 64]
{
    __shared__ __align__(16) float s_w1[D_IN2 * D_HID];   // 32 KB
    __shared__ __align__(16) float s_w2[D_HID * D_HID];   // 16 KB

    const int tid = threadIdx.x;
    for (int i = tid; i < (D_IN2 * D_HID) / 4; i += NBLK)
        reinterpret_cast<float4*>(s_w1)[i] = reinterpret_cast<const float4*>(w1)[i];
    for (int i = tid; i < (D_HID * D_HID) / 4; i += NBLK)
        reinterpret_cast<float4*>(s_w2)[i] = reinterpret_cast<const float4*>(w2)[i];
    __syncthreads();

    const int n = blockIdx.x * NBLK + tid;
    if (n >= N_NODES) return;

    const float4* xn = reinterpret_cast<const float4*>(nf + (size_t)n * D_NODE);
    float4*       xa = reinterpret_cast<float4*>(&g_agg[(size_t)n * D_HID]);

    unsigned long long h2[32];
    {
        const ulonglong2* b1p = reinterpret_cast<const ulonglong2*>(b1);
        #pragma unroll
        for (int i = 0; i < 16; i++) {
            ulonglong2 b = __ldg(&b1p[i]);
            h2[2 * i] = b.x; h2[2 * i + 1] = b.y;
        }
    }
    #pragma unroll 4
    for (int kc = 0; kc < 16; kc++) {
        float4 x = __ldg(&xn[kc]);
        float xv[4] = {x.x, x.y, x.z, x.w};
        #pragma unroll
        for (int kk = 0; kk < 4; kk++) {
            const unsigned long long vv = pack2(xv[kk]);
            const ulonglong2* wr =
                reinterpret_cast<const ulonglong2*>(&s_w1[(kc * 4 + kk) * D_HID]);
            #pragma unroll
            for (int j = 0; j < 16; j++) {
                ulonglong2 w = wr[j];
                fma2(h2[2 * j],     vv, w.x);
                fma2(h2[2 * j + 1], vv, w.y);
            }
        }
    }
    #pragma unroll 4
    for (int kc = 0; kc < 16; kc++) {
        float4 x = xa[kc];
        xa[kc] = make_float4(0.f, 0.f, 0.f, 0.f);   // reset for next replay
        float xv[4] = {x.x, x.y, x.z, x.w};
        #pragma unroll
        for (int kk = 0; kk < 4; kk++) {
            const unsigned long long vv = pack2(xv[kk]);
            const ulonglong2* wr =
                reinterpret_cast<const ulonglong2*>(&s_w1[(D_NODE + kc * 4 + kk) * D_HID]);
            #pragma unroll
            for (int j = 0; j < 16; j++) {
                ulonglong2 w = wr[j];
                fma2(h2[2 * j],     vv, w.x);
                fma2(h2[2 * j + 1], vv, w.y);
            }
        }
    }

    float h[D_HID];
    #pragma unroll
    for (int i = 0; i < 32; i++) {
        float lo, hi;
        unpack2(h2[i], lo, hi);
        h[2 * i]     = fmaxf(lo, 0.f);
        h[2 * i + 1] = fmaxf(hi, 0.f);
    }

    float* outp = out + (size_t)n * D_HID;
    #pragma unroll
    for (int jc = 0; jc < 4; jc++) {
        unsigned long long acc2[8];
        {
            const ulonglong2* b2p = reinterpret_cast<const ulonglong2*>(&b2[jc * 16]);
            #pragma unroll
            for (int i = 0; i < 4; i++) {
                ulonglong2 b = __ldg(&b2p[i]);
                acc2[2 * i] = b.x; acc2[2 * i + 1] = b.y;
            }
        }
        #pragma unroll 8
        for (int k = 0; k < D_HID; k++) {
            const unsigned long long vv = pack2(h[k]);
            const ulonglong2* wr =
                reinterpret_cast<const ulonglong2*>(&s_w2[k * D_HID + jc * 16]);
            #pragma unroll
            for (int i = 0; i < 4; i++) {
                ulonglong2 w = wr[i];
                fma2(acc2[2 * i],     vv, w.x);
                fma2(acc2[2 * i + 1], vv, w.y);
            }
        }
        float acc[16];
        #pragma unroll
        for (int i = 0; i < 8; i++) unpack2(acc2[i], acc[2 * i], acc[2 * i + 1]);
        #pragma unroll
        for (int j = 0; j < 16; j += 4) {
            float4 v = make_float4(acc[j], acc[j + 1], acc[j + 2], acc[j + 3]);
            *reinterpret_cast<float4*>(&outp[jc * 16 + j]) = v;
        }
    }
}

// ---------------------------------------------------------------------------
// Launch. Input order: node_features, edge_features, edge_index,
// w_m1, b_m1, w_m2, b_m2, w_u1, b_u1, w_u2, b_u2. Output: float32 [N, 64].
// ---------------------------------------------------------------------------
extern "C" void kernel_launch(void* const* d_in, const int* in_sizes, int n_in,
                              void* d_out, int out_size) {
    const float* nf   = (const float*)d_in[0];
    const float* ef   = (const float*)d_in[1];
    const int*   ei   = (const int*)  d_in[2];
    const float* w_m1 = (const float*)d_in[3];
    const float* b_m1 = (const float*)d_in[4];
    const float* w_m2 = (const float*)d_in[5];
    const float* b_m2 = (const float*)d_in[6];
    const float* w_u1 = (const float*)d_in[7];
    const float* b_u1 = (const float*)d_in[8];
    const float* w_u2 = (const float*)d_in[9];
    const float* b_u2 = (const float*)d_in[10];
    float* out = (float*)d_out;

    (void)in_sizes; (void)n_in; (void)out_size;

    // Device-state (not stream) call: capture-safe, idempotent.
    cudaFuncSetAttribute(edge_kernel,
                         cudaFuncAttributeMaxDynamicSharedMemorySize,
                         EDGE_SMEM_BYTES);

    {
        const int grid = (N_EDGES + TM - 1) / TM;
        edge_kernel<<<grid, ETHREADS, EDGE_SMEM_BYTES>>>(
            nf, ef, ei, w_m1, b_m1, w_m2, b_m2);
    }
    {
        const int grid = (N_NODES + NBLK - 1) / NBLK;
        node_kernel<<<grid, NBLK>>>(nf, w_u1, b_u1, w_u2, b_u2, out);
    }
}

// round 14
// speedup vs baseline: 1.4462x; 1.0133x over previous
#include <cuda_runtime.h>
#include <cuda_bf16.h>

#define N_NODES 50000
#define N_EDGES 1250000
#define D_NODE  64
#define D_EDGE  16
#define D_HID   64
#define K1      80    // D_NODE + D_EDGE
#define K2      128   // D_NODE + D_HID (node-update input)

// ---- shared tiling params (both kernels) ----
#define TM      128   // rows (edges/nodes) per block
#define LDX     132   // padded row stride (floats) for transposed tiles
#define ETHREADS 256  // 16 x 16

// Scratch for segment-sum aggregation. Zero-initialized at module load;
// node_tile_kernel re-zeroes each row as it consumes it, so the invariant
// "g_agg == 0 at kernel_launch entry" holds across graph replays.
__device__ __align__(16) float g_agg[(size_t)N_NODES * D_HID];

// ---- packed fp32x2 helpers (sm_100+: dual-lane FFMA via PTX f32x2) --------
__device__ __forceinline__ unsigned long long pack2(float v) {
    unsigned long long r;
    unsigned int b = __float_as_uint(v);
    asm("mov.b64 %0, {%1, %1};" : "=l"(r) : "r"(b));
    return r;
}
__device__ __forceinline__ void fma2(unsigned long long& d,
                                     unsigned long long a,
                                     unsigned long long b) {
    asm("fma.rn.f32x2 %0, %1, %2, %0;" : "+l"(d) : "l"(a), "l"(b));
}
__device__ __forceinline__ void unpack2(unsigned long long v, float& lo, float& hi) {
    unsigned int l, h;
    asm("mov.b64 {%0, %1}, %2;" : "=r"(l), "=r"(h) : "l"(v));
    lo = __uint_as_float(l);
    hi = __uint_as_float(h);
}
__device__ __forceinline__ void red_add_v4(float* p, float a, float b, float c, float d) {
    asm volatile("red.global.add.v4.f32 [%0], {%1, %2, %3, %4};"
                 :: "l"(p), "f"(a), "f"(b), "f"(c), "f"(d) : "memory");
}

// ---- edge kernel smem layout (floats) ----
#define SX_OFF   0
#define SW1_OFF  (K1 * LDX)
#define SW2_OFF  (SW1_OFF + K1 * D_HID)
#define SRC_OFF  (SW2_OFF + D_HID * D_HID)
#define DST_OFF  (SRC_OFF + TM)
#define EDGE_SMEM_FLOATS (DST_OFF + TM)
#define EDGE_SMEM_BYTES  (EDGE_SMEM_FLOATS * 4)   // 80128

// ---- node kernel smem layout (floats) ----
#define NSX_OFF   0
#define NSW1_OFF  (K2 * LDX)                       // 16896
#define NSW2_OFF  (NSW1_OFF + K2 * D_HID)          // 25088
#define NODE_SMEM_FLOATS (NSW2_OFF + D_HID * D_HID)
#define NODE_SMEM_BYTES  (NODE_SMEM_FLOATS * 4)    // 116736

// ---------------------------------------------------------------------------
// No-op pad kernel: aligns ncu's "-s 5 -c 1" capture (index 5 mod 4 == 1)
// onto edge_kernel. ~2us per launch.
// ---------------------------------------------------------------------------
__global__ void prof_pad_kernel() {}

// ---------------------------------------------------------------------------
// Phase 1: tiled edge message MLP + scatter-add.
// Block = 128 edges; thread (tx,ty) computes an 8-edge x 4-hid tile.
// Inputs staged transposed (xT[k][m]) so f32x2 packs over m with zero movs.
// ---------------------------------------------------------------------------
__global__ __launch_bounds__(ETHREADS, 2)
void edge_kernel(const float* __restrict__ nf,   // [N, 64]
                 const float* __restrict__ ef,   // [E, 16]
                 const int*   __restrict__ ei,   // [2, E]
                 const float* __restrict__ w1,   // [80, 64]
                 const float* __restrict__ b1,   // [64]
                 const float* __restrict__ w2,   // [64, 64]
                 const float* __restrict__ b2)   // [64]
{
    extern __shared__ __align__(16) float smem[];
    float* sx  = smem + SX_OFF;
    float* sw1 = smem + SW1_OFF;
    float* sw2 = smem + SW2_OFF;
    int*   ssrc = (int*)(smem + SRC_OFF);
    int*   sdst = (int*)(smem + DST_OFF);

    const int tid = threadIdx.x;
    const int tx = tid & 15;        // output-column group: cols 4tx..4tx+3
    const int ty = tid >> 4;        // edge group: edges 8ty..8ty+7
    const int edge_base = blockIdx.x * TM;

    // --- stage edge indices (clamped; invalid edges masked at scatter) ---
    {
        int m = tid & 127;
        int e = edge_base + m;
        if (e >= N_EDGES) e = N_EDGES - 1;
        if (tid < 128) ssrc[m] = __ldg(&ei[e]);
        else           sdst[m] = __ldg(&ei[N_EDGES + e]);
    }
    // --- stage weights (no dependence on indices) ---
    for (int i = tid; i < (K1 * D_HID) / 4; i += ETHREADS)
        reinterpret_cast<float4*>(sw1)[i] = __ldg(&reinterpret_cast<const float4*>(w1)[i]);
    for (int i = tid; i < (D_HID * D_HID) / 4; i += ETHREADS)
        reinterpret_cast<float4*>(sw2)[i] = __ldg(&reinterpret_cast<const float4*>(w2)[i]);
    __syncthreads();

    // --- gather + transpose inputs: xT[k][m], k = [node 64 | edge 16] ---
    {
        int m    = tid & 127;
        int half = tid >> 7;        // 2 threads per edge
        const float4* np = reinterpret_cast<const float4*>(nf + (size_t)ssrc[m] * D_NODE);
        #pragma unroll
        for (int q = 0; q < 8; q++) {
            int qq = half * 8 + q;
            float4 v = __ldg(&np[qq]);
            sx[(qq * 4 + 0) * LDX + m] = v.x;
            sx[(qq * 4 + 1) * LDX + m] = v.y;
            sx[(qq * 4 + 2) * LDX + m] = v.z;
            sx[(qq * 4 + 3) * LDX + m] = v.w;
        }
        int e = edge_base + m;
        if (e >= N_EDGES) e = N_EDGES - 1;
        const float4* ep = reinterpret_cast<const float4*>(ef + (size_t)e * D_EDGE);
        #pragma unroll
        for (int q = 0; q < 2; q++) {
            int qq = half * 2 + q;
            float4 v = __ldg(&ep[qq]);
            sx[(D_NODE + qq * 4 + 0) * LDX + m] = v.x;
            sx[(D_NODE + qq * 4 + 1) * LDX + m] = v.y;
            sx[(D_NODE + qq * 4 + 2) * LDX + m] = v.z;
            sx[(D_NODE + qq * 4 + 3) * LDX + m] = v.w;
        }
    }
    __syncthreads();

    const float* xbase = sx + ty * 8;

    // --- layer 1: acc[n][mq] over K1=80, f32x2 packed over m ---
    unsigned long long acc[4][4];
    {
        float4 bv = __ldg(reinterpret_cast<const float4*>(b1 + tx * 4));
        unsigned long long b0 = pack2(bv.x), b1p = pack2(bv.y),
                           b2p = pack2(bv.z), b3p = pack2(bv.w);
        #pragma unroll
        for (int mq = 0; mq < 4; mq++) {
            acc[0][mq] = b0; acc[1][mq] = b1p; acc[2][mq] = b2p; acc[3][mq] = b3p;
        }
    }
    #pragma unroll 2
    for (int k = 0; k < K1; k++) {
        ulonglong2 xa = *reinterpret_cast<const ulonglong2*>(xbase + k * LDX);
        ulonglong2 xb = *reinterpret_cast<const ulonglong2*>(xbase + k * LDX + 4);
        float4 wv = *reinterpret_cast<const float4*>(sw1 + k * D_HID + tx * 4);
        unsigned long long w0 = pack2(wv.x), w1p = pack2(wv.y),
                           w2p = pack2(wv.z), w3p = pack2(wv.w);
        fma2(acc[0][0], xa.x, w0);  fma2(acc[0][1], xa.y, w0);
        fma2(acc[0][2], xb.x, w0);  fma2(acc[0][3], xb.y, w0);
        fma2(acc[1][0], xa.x, w1p); fma2(acc[1][1], xa.y, w1p);
        fma2(acc[1][2], xb.x, w1p); fma2(acc[1][3], xb.y, w1p);
        fma2(acc[2][0], xa.x, w2p); fma2(acc[2][1], xa.y, w2p);
        fma2(acc[2][2], xb.x, w2p); fma2(acc[2][3], xb.y, w2p);
        fma2(acc[3][0], xa.x, w3p); fma2(acc[3][1], xa.y, w3p);
        fma2(acc[3][2], xb.x, w3p); fma2(acc[3][3], xb.y, w3p);
    }
    __syncthreads();   // everyone done reading sx

    // --- relu + restage h transposed: hT[k2][m], k2 = 4tx+n ---
    #pragma unroll
    for (int n = 0; n < 4; n++) {
        #pragma unroll
        for (int mq2 = 0; mq2 < 2; mq2++) {
            float f0, f1, f2, f3;
            unpack2(acc[n][2 * mq2],     f0, f1);
            unpack2(acc[n][2 * mq2 + 1], f2, f3);
            float4 v = make_float4(fmaxf(f0, 0.f), fmaxf(f1, 0.f),
                                   fmaxf(f2, 0.f), fmaxf(f3, 0.f));
            *reinterpret_cast<float4*>(sx + (tx * 4 + n) * LDX + ty * 8 + mq2 * 4) = v;
        }
    }
    __syncthreads();

    // --- layer 2: same tile shape over K=64 ---
    unsigned long long acc2[4][4];
    {
        float4 bv = __ldg(reinterpret_cast<const float4*>(b2 + tx * 4));
        unsigned long long b0 = pack2(bv.x), b1p = pack2(bv.y),
                           b2p = pack2(bv.z), b3p = pack2(bv.w);
        #pragma unroll
        for (int mq = 0; mq < 4; mq++) {
            acc2[0][mq] = b0; acc2[1][mq] = b1p; acc2[2][mq] = b2p; acc2[3][mq] = b3p;
        }
    }
    #pragma unroll 2
    for (int k = 0; k < D_HID; k++) {
        ulonglong2 xa = *reinterpret_cast<const ulonglong2*>(xbase + k * LDX);
        ulonglong2 xb = *reinterpret_cast<const ulonglong2*>(xbase + k * LDX + 4);
        float4 wv = *reinterpret_cast<const float4*>(sw2 + k * D_HID + tx * 4);
        unsigned long long w0 = pack2(wv.x), w1p = pack2(wv.y),
                           w2p = pack2(wv.z), w3p = pack2(wv.w);
        fma2(acc2[0][0], xa.x, w0);  fma2(acc2[0][1], xa.y, w0);
        fma2(acc2[0][2], xb.x, w0);  fma2(acc2[0][3], xb.y, w0);
        fma2(acc2[1][0], xa.x, w1p); fma2(acc2[1][1], xa.y, w1p);
        fma2(acc2[1][2], xb.x, w1p); fma2(acc2[1][3], xb.y, w1p);
        fma2(acc2[2][0], xa.x, w2p); fma2(acc2[2][1], xa.y, w2p);
        fma2(acc2[2][2], xb.x, w2p); fma2(acc2[2][3], xb.y, w2p);
        fma2(acc2[3][0], xa.x, w3p); fma2(acc2[3][1], xa.y, w3p);
        fma2(acc2[3][2], xb.x, w3p); fma2(acc2[3][3], xb.y, w3p);
    }

    // --- scatter: lanes tx=0..15 cover one edge's contiguous 64-float row ---
    #pragma unroll
    for (int mq = 0; mq < 4; mq++) {        // m pair (2mq, 2mq+1) within tile
        float a0, c0, a1, c1, a2, c2, a3, c3;
        unpack2(acc2[0][mq], a0, c0);
        unpack2(acc2[1][mq], a1, c1);
        unpack2(acc2[2][mq], a2, c2);
        unpack2(acc2[3][mq], a3, c3);
        int m0 = ty * 8 + 2 * mq;
        int e0 = edge_base + m0;
        if (e0 < N_EDGES)
            red_add_v4(&g_agg[(size_t)sdst[m0] * D_HID + tx * 4], a0, a1, a2, a3);
        if (e0 + 1 < N_EDGES)
            red_add_v4(&g_agg[(size_t)sdst[m0 + 1] * D_HID + tx * 4], c0, c1, c2, c3);
    }
}

// ---------------------------------------------------------------------------
// Phase 2: tiled node update MLP. Same tile structure as edge_kernel but
// K=128 (= node_feat ++ aggregated), coalesced gather, direct stores.
// Zeroes each consumed g_agg row (read-then-zero by the same thread; clamped
// tail threads never zero, and their outputs are masked at the store).
// ---------------------------------------------------------------------------
__global__ __launch_bounds__(ETHREADS)
void node_tile_kernel(const float* __restrict__ nf,   // [N, 64]
                      const float* __restrict__ w1,   // [128, 64]
                      const float* __restrict__ b1,   // [64]
                      const float* __restrict__ w2,   // [64, 64]
                      const float* __restrict__ b2,   // [64]
                      float*       __restrict__ out)  // [N, 64]
{
    extern __shared__ __align__(16) float smem[];
    float* sx  = smem + NSX_OFF;
    float* sw1 = smem + NSW1_OFF;
    float* sw2 = smem + NSW2_OFF;

    const int tid = threadIdx.x;
    const int tx = tid & 15;
    const int ty = tid >> 4;
    const int node_base = blockIdx.x * TM;

    // --- stage weights ---
    for (int i = tid; i < (K2 * D_HID) / 4; i += ETHREADS)
        reinterpret_cast<float4*>(sw1)[i] = __ldg(&reinterpret_cast<const float4*>(w1)[i]);
    for (int i = tid; i < (D_HID * D_HID) / 4; i += ETHREADS)
        reinterpret_cast<float4*>(sw2)[i] = __ldg(&reinterpret_cast<const float4*>(w2)[i]);

    // --- gather + transpose: xT[k][m], k = [node 64 | agg 64] ---
    {
        int m    = tid & 127;
        int half = tid >> 7;        // 2 threads per node
        int nd = node_base + m;
        bool valid = nd < N_NODES;
        if (!valid) nd = N_NODES - 1;

        const float4* np = reinterpret_cast<const float4*>(nf + (size_t)nd * D_NODE);
        #pragma unroll
        for (int q = 0; q < 8; q++) {
            int qq = half * 8 + q;
            float4 v = __ldg(&np[qq]);
            sx[(qq * 4 + 0) * LDX + m] = v.x;
            sx[(qq * 4 + 1) * LDX + m] = v.y;
            sx[(qq * 4 + 2) * LDX + m] = v.z;
            sx[(qq * 4 + 3) * LDX + m] = v.w;
        }
        float4* ap = reinterpret_cast<float4*>(&g_agg[(size_t)nd * D_HID]);
        #pragma unroll
        for (int q = 0; q < 8; q++) {
            int qq = half * 8 + q;
            float4 v = ap[qq];
            if (valid) ap[qq] = make_float4(0.f, 0.f, 0.f, 0.f);   // reset for next replay
            sx[(D_NODE + qq * 4 + 0) * LDX + m] = v.x;
            sx[(D_NODE + qq * 4 + 1) * LDX + m] = v.y;
            sx[(D_NODE + qq * 4 + 2) * LDX + m] = v.z;
            sx[(D_NODE + qq * 4 + 3) * LDX + m] = v.w;
        }
    }
    __syncthreads();

    const float* xbase = sx + ty * 8;

    // --- layer 1 over K2=128 ---
    unsigned long long acc[4][4];
    {
        float4 bv = __ldg(reinterpret_cast<const float4*>(b1 + tx * 4));
        unsigned long long b0 = pack2(bv.x), b1p = pack2(bv.y),
                           b2p = pack2(bv.z), b3p = pack2(bv.w);
        #pragma unroll
        for (int mq = 0; mq < 4; mq++) {
            acc[0][mq] = b0; acc[1][mq] = b1p; acc[2][mq] = b2p; acc[3][mq] = b3p;
        }
    }
    #pragma unroll 2
    for (int k = 0; k < K2; k++) {
        ulonglong2 xa = *reinterpret_cast<const ulonglong2*>(xbase + k * LDX);
        ulonglong2 xb = *reinterpret_cast<const ulonglong2*>(xbase + k * LDX + 4);
        float4 wv = *reinterpret_cast<const float4*>(sw1 + k * D_HID + tx * 4);
        unsigned long long w0 = pack2(wv.x), w1p = pack2(wv.y),
                           w2p = pack2(wv.z), w3p = pack2(wv.w);
        fma2(acc[0][0], xa.x, w0);  fma2(acc[0][1], xa.y, w0);
        fma2(acc[0][2], xb.x, w0);  fma2(acc[0][3], xb.y, w0);
        fma2(acc[1][0], xa.x, w1p); fma2(acc[1][1], xa.y, w1p);
        fma2(acc[1][2], xb.x, w1p); fma2(acc[1][3], xb.y, w1p);
        fma2(acc[2][0], xa.x, w2p); fma2(acc[2][1], xa.y, w2p);
        fma2(acc[2][2], xb.x, w2p); fma2(acc[2][3], xb.y, w2p);
        fma2(acc[3][0], xa.x, w3p); fma2(acc[3][1], xa.y, w3p);
        fma2(acc[3][2], xb.x, w3p); fma2(acc[3][3], xb.y, w3p);
    }
    __syncthreads();

    // --- relu + restage hT ---
    #pragma unroll
    for (int n = 0; n < 4; n++) {
        #pragma unroll
        for (int mq2 = 0; mq2 < 2; mq2++) {
            float f0, f1, f2, f3;
            unpack2(acc[n][2 * mq2],     f0, f1);
            unpack2(acc[n][2 * mq2 + 1], f2, f3);
            float4 v = make_float4(fmaxf(f0, 0.f), fmaxf(f1, 0.f),
                                   fmaxf(f2, 0.f), fmaxf(f3, 0.f));
            *reinterpret_cast<float4*>(sx + (tx * 4 + n) * LDX + ty * 8 + mq2 * 4) = v;
        }
    }
    __syncthreads();

    // --- layer 2 over K=64 ---
    unsigned long long acc2[4][4];
    {
        float4 bv = __ldg(reinterpret_cast<const float4*>(b2 + tx * 4));
        unsigned long long b0 = pack2(bv.x), b1p = pack2(bv.y),
                           b2p = pack2(bv.z), b3p = pack2(bv.w);
        #pragma unroll
        for (int mq = 0; mq < 4; mq++) {
            acc2[0][mq] = b0; acc2[1][mq] = b1p; acc2[2][mq] = b2p; acc2[3][mq] = b3p;
        }
    }
    #pragma unroll 2
    for (int k = 0; k < D_HID; k++) {
        ulonglong2 xa = *reinterpret_cast<const ulonglong2*>(xbase + k * LDX);
        ulonglong2 xb = *reinterpret_cast<const ulonglong2*>(xbase + k * LDX + 4);
        float4 wv = *reinterpret_cast<const float4*>(sw2 + k * D_HID + tx * 4);
        unsigned long long w0 = pack2(wv.x), w1p = pack2(wv.y),
                           w2p = pack2(wv.z), w3p = pack2(wv.w);
        fma2(acc2[0][0], xa.x, w0);  fma2(acc2[0][1], xa.y, w0);
        fma2(acc2[0][2], xb.x, w0);  fma2(acc2[0][3], xb.y, w0);
        fma2(acc2[1][0], xa.x, w1p); fma2(acc2[1][1], xa.y, w1p);
        fma2(acc2[1][2], xb.x, w1p); fma2(acc2[1][3], xb.y, w1p);
        fma2(acc2[2][0], xa.x, w2p); fma2(acc2[2][1], xa.y, w2p);
        fma2(acc2[2][2], xb.x, w2p); fma2(acc2[2][3], xb.y, w2p);
        fma2(acc2[3][0], xa.x, w3p); fma2(acc2[3][1], xa.y, w3p);
        fma2(acc2[3][2], xb.x, w3p); fma2(acc2[3][3], xb.y, w3p);
    }

    // --- direct store: lanes tx=0..15 cover one node's 64-float row ---
    #pragma unroll
    for (int mq = 0; mq < 4; mq++) {
        float a0, c0, a1, c1, a2, c2, a3, c3;
        unpack2(acc2[0][mq], a0, c0);
        unpack2(acc2[1][mq], a1, c1);
        unpack2(acc2[2][mq], a2, c2);
        unpack2(acc2[3][mq], a3, c3);
        int m0 = node_base + ty * 8 + 2 * mq;
        if (m0 < N_NODES)
            *reinterpret_cast<float4*>(out + (size_t)m0 * D_HID + tx * 4) =
                make_float4(a0, a1, a2, a3);
        if (m0 + 1 < N_NODES)
            *reinterpret_cast<float4*>(out + (size_t)(m0 + 1) * D_HID + tx * 4) =
                make_float4(c0, c1, c2, c3);
    }
}

// ---------------------------------------------------------------------------
// Launch. Input order: node_features, edge_features, edge_index,
// w_m1, b_m1, w_m2, b_m2, w_u1, b_u1, w_u2, b_u2. Output: float32 [N, 64].
// Launch period = 4 with edge_kernel at index 1 so ncu (-s 5) captures it.
// ---------------------------------------------------------------------------
extern "C" void kernel_launch(void* const* d_in, const int* in_sizes, int n_in,
                              void* d_out, int out_size) {
    const float* nf   = (const float*)d_in[0];
    const float* ef   = (const float*)d_in[1];
    const int*   ei   = (const int*)  d_in[2];
    const float* w_m1 = (const float*)d_in[3];
    const float* b_m1 = (const float*)d_in[4];
    const float* w_m2 = (const float*)d_in[5];
    const float* b_m2 = (const float*)d_in[6];
    const float* w_u1 = (const float*)d_in[7];
    const float* b_u1 = (const float*)d_in[8];
    const float* w_u2 = (const float*)d_in[9];
    const float* b_u2 = (const float*)d_in[10];
    float* out = (float*)d_out;

    (void)in_sizes; (void)n_in; (void)out_size;

    // Device-state (not stream) calls: capture-safe, idempotent.
    cudaFuncSetAttribute(edge_kernel,
                         cudaFuncAttributeMaxDynamicSharedMemorySize,
                         EDGE_SMEM_BYTES);
    cudaFuncSetAttribute(node_tile_kernel,
                         cudaFuncAttributeMaxDynamicSharedMemorySize,
                         NODE_SMEM_BYTES);

    prof_pad_kernel<<<1, 1>>>();
    {
        const int grid = (N_EDGES + TM - 1) / TM;
        edge_kernel<<<grid, ETHREADS, EDGE_SMEM_BYTES>>>(
            nf, ef, ei, w_m1, b_m1, w_m2, b_m2);
    }
    {
        const int grid = (N_NODES + TM - 1) / TM;
        node_tile_kernel<<<grid, ETHREADS, NODE_SMEM_BYTES>>>(
            nf, w_u1, b_u1, w_u2, b_u2, out);
    }
    prof_pad_kernel<<<1, 1>>>();
}